// round 10
// baseline (speedup 1.0000x reference)
#include <cuda_runtime.h>
#include <cuda_bf16.h>
#include <math.h>

#define TT 512
#define BB 128
#define DD 256
#define HH 512
#define G4 2048
#define MID 512
#define MAXROWS (TT*BB)

typedef unsigned long long ull;
typedef unsigned int u32;

__device__ __forceinline__ ull ffma2(ull a, ull b, ull c) {
    ull d; asm("fma.rn.f32x2 %0, %1, %2, %3;" : "=l"(d) : "l"(a), "l"(b), "l"(c)); return d;
}
__device__ __forceinline__ ull pk2(float lo, float hi) {
    ull d; asm("mov.b64 %0, {%1, %2};" : "=l"(d) : "f"(lo), "f"(hi)); return d;
}
__device__ __forceinline__ float2 unpk(ull v) {
    float2 r; asm("mov.b64 {%0, %1}, %2;" : "=f"(r.x), "=f"(r.y) : "l"(v)); return r;
}
__device__ __forceinline__ float fast_tanh(float x) {
    float y; asm("tanh.approx.f32 %0, %1;" : "=f"(y) : "f"(x)); return y;
}
__device__ __forceinline__ float sigf(float x) { return 0.5f * fast_tanh(0.5f * x) + 0.5f; }
__device__ __forceinline__ u32 tf32r(float x) {
    u32 y; asm("cvt.rna.tf32.f32 %0, %1;" : "=r"(y) : "f"(x)); return y;
}
__device__ __forceinline__ void mma8(float* d, const u32* a, const u32* b) {
    asm("mma.sync.aligned.m16n8k8.row.col.f32.tf32.tf32.f32 "
        "{%0,%1,%2,%3}, {%4,%5,%6,%7}, {%8,%9}, {%0,%1,%2,%3};"
        : "+f"(d[0]), "+f"(d[1]), "+f"(d[2]), "+f"(d[3])
        : "r"(a[0]), "r"(a[1]), "r"(a[2]), "r"(a[3]), "r"(b[0]), "r"(b[1]));
}

// ---------- scratch ----------
__device__ float g_xw[(size_t)MAXROWS * G4];
__device__ float g_hs[(size_t)MAXROWS * HH];
__device__ float g_hb[2][BB * HH];
__device__ int   g_offs[BB + 1];
__device__ int   g_rowidx[MAXROWS];
__device__ unsigned g_bar;
__device__ float g_inp[(size_t)MAXROWS * (DD + HH)];
__device__ float g_m1[(size_t)MAXROWS * MID];
__device__ float g_m2[(size_t)MAXROWS * MID];

// ---------- setup ----------
__global__ void scan_kernel(const int* __restrict__ len) {
    __shared__ int sl[BB];
    int tid = threadIdx.x;
    if (tid < BB) sl[tid] = len[tid];
    __syncthreads();
    if (tid == 0) {
        int s = 0;
        for (int b = 0; b < BB; b++) { g_offs[b] = s; s += sl[b]; }
        g_offs[BB] = s;
        g_bar = 0u;
    }
}
__global__ void init_kernel(const float* __restrict__ h0) {
    int i = blockIdx.x * 256 + threadIdx.x;
    if (i < BB * HH) g_hb[0][i] = h0[i];
}
__global__ void rowmap_kernel(const int* __restrict__ len) {
    int b = blockIdx.x;
    int off = g_offs[b];
    int L = len[b];
    for (int i = threadIdx.x; i < L; i += blockDim.x)
        g_rowidx[off + i] = i * BB + b;
}

// ---------- HMMA GEMM: C[M,N] = act(A[gather][K] @ Wsel[N,K]^T + b1 (+b2)) ----------
// 128x128 tile, 256 thr (8 warps, warp tile 32x64), 3xTF32 split via mma.sync.
// SMEM fragment layout: A [buf][k8][mt][lane*4+r] (blk 132f), B [buf][k8][nt][lane*2+r] (blk 66f).
#define ABLK 132
#define BBLK 66
#define AH_OFF 0
#define AL_OFF 4224
#define BH_OFF 8448
#define BL_OFF 12672
#define TG_SMEM (16896 * 4)
__global__ __launch_bounds__(256, 1) void tgemm_mma(
    const float* __restrict__ A, const int* __restrict__ rowidx,
    const float* __restrict__ W,
    const float* __restrict__ b1, const float* __restrict__ b2,
    float* __restrict__ C, int M, int N, int K, int act, int perm)
{
    extern __shared__ u32 sf[];
    const int tid = threadIdx.x, wid = tid >> 5, lane = tid & 31;
    const int row0 = blockIdx.x * 128, col0 = blockIdx.y * 128;
    const int wm = wid & 3, wn = wid >> 2;
    const int g = lane >> 2, tig = lane & 3;

    // ---- staging role ----
    const int rowl = tid >> 1;          // 0..127
    const int k8s  = tid & 1;           // which k8 of the 16-chunk
    const int arow = row0 + rowl;
    const int agc  = arow < M ? arow : 0;
    const int ag   = rowidx ? rowidx[agc] : agc;
    const float4* Ap4 = (const float4*)(A + (size_t)ag * K);
    const int wc = col0 + rowl;
    const int wr = perm ? ((wc & 3) * HH + (wc >> 2)) : wc;
    const float4* Wp4 = (const float4*)(W + (size_t)wr * K);
    // A dest indices: mt block + element offsets
    const int amt   = rowl >> 4;
    const int arr   = rowl & 15;
    const int ag8   = arr & 7, arb = arr >> 3;
    const int nt_s  = rowl >> 3, bg = rowl & 7;

    float acc[2][8][4];
#pragma unroll
    for (int mt = 0; mt < 2; mt++)
#pragma unroll
        for (int nt = 0; nt < 8; nt++)
#pragma unroll
            for (int q = 0; q < 4; q++) acc[mt][nt][q] = 0.0f;

    const int NC = K / 16;
    float4 qa0, qa1, qw0, qw1;
    // prefetch chunk 0
    qa0 = Ap4[k8s * 2];     qa1 = Ap4[k8s * 2 + 1];
    qw0 = Wp4[k8s * 2];     qw1 = Wp4[k8s * 2 + 1];

    for (int c = 0; c < NC; c++) {
        // ---- STS chunk c into buf (c&1) ----
        {
            const int bufo = (c & 1);
            float av[8] = {qa0.x,qa0.y,qa0.z,qa0.w,qa1.x,qa1.y,qa1.z,qa1.w};
            float wv[8] = {qw0.x,qw0.y,qw0.z,qw0.w,qw1.x,qw1.y,qw1.z,qw1.w};
            u32 abase = (u32)(((bufo * 2 + k8s) * 8 + amt) * ABLK);
            u32 bbase = (u32)(((bufo * 2 + k8s) * 16 + nt_s) * BBLK);
#pragma unroll
            for (int cc = 0; cc < 8; cc++) {
                int alane = ag8 * 4 + (cc & 3);
                int ar    = arb + 2 * (cc >> 2);
                u32 hi = tf32r(av[cc]);
                u32 lo = tf32r(av[cc] - __uint_as_float(hi));
                sf[AH_OFF + abase + alane * 4 + ar] = hi;
                sf[AL_OFF + abase + alane * 4 + ar] = lo;
                int blane = bg * 4 + (cc & 3);
                int br    = cc >> 2;
                u32 whi = tf32r(wv[cc]);
                u32 wlo = tf32r(wv[cc] - __uint_as_float(whi));
                sf[BH_OFF + bbase + blane * 2 + br] = whi;
                sf[BL_OFF + bbase + blane * 2 + br] = wlo;
            }
        }
        // prefetch chunk c+1
        if (c + 1 < NC) {
            int kb4 = (c + 1) * 4 + k8s * 2;
            qa0 = Ap4[kb4]; qa1 = Ap4[kb4 + 1];
            qw0 = Wp4[kb4]; qw1 = Wp4[kb4 + 1];
        }
        __syncthreads();
        // ---- compute chunk c from buf (c&1) ----
        {
            const int bufo = (c & 1);
#pragma unroll
            for (int k8 = 0; k8 < 2; k8++) {
                u32 ah[2][4], al[2][4];
                int ao = ((bufo * 2 + k8) * 8 + wm * 2) * ABLK + lane * 4;
                *(uint4*)ah[0] = *(const uint4*)&sf[AH_OFF + ao];
                *(uint4*)ah[1] = *(const uint4*)&sf[AH_OFF + ao + ABLK];
                *(uint4*)al[0] = *(const uint4*)&sf[AL_OFF + ao];
                *(uint4*)al[1] = *(const uint4*)&sf[AL_OFF + ao + ABLK];
                u32 bh[8][2], bl[8][2];
                int bo = ((bufo * 2 + k8) * 16 + wn * 8) * BBLK + lane * 2;
#pragma unroll
                for (int nt = 0; nt < 8; nt++) {
                    *(uint2*)bh[nt] = *(const uint2*)&sf[BH_OFF + bo + nt * BBLK];
                    *(uint2*)bl[nt] = *(const uint2*)&sf[BL_OFF + bo + nt * BBLK];
                }
#pragma unroll
                for (int mt = 0; mt < 2; mt++)
#pragma unroll
                    for (int nt = 0; nt < 8; nt++) {
                        mma8(acc[mt][nt], ah[mt], bh[nt]);
                        mma8(acc[mt][nt], ah[mt], bl[nt]);
                        mma8(acc[mt][nt], al[mt], bh[nt]);
                    }
            }
        }
        __syncthreads();
    }

    // ---- epilogue ----
    const int m0 = row0 + wm * 32;
    const int n0 = col0 + wn * 64;
#pragma unroll
    for (int mt = 0; mt < 2; mt++) {
        int r0 = m0 + mt * 16 + g;
        int r1 = r0 + 8;
#pragma unroll
        for (int nt = 0; nt < 8; nt++) {
            int cb = n0 + nt * 8 + tig * 2;
            int ci0 = perm ? ((cb & 3) * HH + (cb >> 2)) : cb;
            int ci1 = perm ? (((cb + 1) & 3) * HH + ((cb + 1) >> 2)) : (cb + 1);
            float bs0 = b1[ci0] + (b2 ? b2[ci0] : 0.0f);
            float bs1 = b1[ci1] + (b2 ? b2[ci1] : 0.0f);
            float v0 = acc[mt][nt][0] + bs0, v1 = acc[mt][nt][1] + bs1;
            float v2 = acc[mt][nt][2] + bs0, v3 = acc[mt][nt][3] + bs1;
            if (act == 1) {
                v0 = fmaxf(v0, 0.f); v1 = fmaxf(v1, 0.f);
                v2 = fmaxf(v2, 0.f); v3 = fmaxf(v3, 0.f);
            }
            if (r0 < M) *(float2*)&C[(size_t)r0 * N + cb] = make_float2(v0, v1);
            if (r1 < M) *(float2*)&C[(size_t)r1 * N + cb] = make_float2(v2, v3);
        }
    }
}

// ---------- persistent LSTM (unchanged from R8 + nanosleep) ----------
__global__ __launch_bounds__(256, 1) void lstm_persist(
    const float* __restrict__ W_hh, const int* __restrict__ len)
{
    extern __shared__ char smem[];
    ull* sWp = (ull*)smem;
    ull* sH  = (ull*)(smem + 65536);
    ull* red = sH;

    const int tid = threadIdx.x;
    const int u0      = (blockIdx.x >> 1) * 8;
    const int rowbase = (blockIdx.x & 1) * 64;
    const int kh   = tid >> 7;
    const int tid2 = tid & 127;
    const int tx   = tid2 & 7;
    const int ty4  = (tid2 >> 3) * 4;
    const int u    = u0 + tx;

    for (int idx = tid; idx < 256 * 32; idx += 256) {
        int kp = idx >> 5, c = idx & 31;
        const float* w = W_hh + (size_t)((c & 3) * HH + u0 + (c >> 2)) * HH + kp * 2;
        sWp[idx] = pk2(w[0], w[1]);
    }

    int offs_r[4], len_r[4];
    float creg[4] = {0.f, 0.f, 0.f, 0.f};
    if (kh == 0) {
#pragma unroll
        for (int r = 0; r < 4; r++) {
            int row = rowbase + ty4 + r;
            offs_r[r] = g_offs[row];
            len_r[r]  = len[row];
        }
    }
    const int sr0 = tid >> 3, skq = tid & 7;
    const int sr1 = sr0 + 32;
    __syncthreads();

    for (int t = 0; t < TT; t++) {
        const float* hprev = g_hb[t & 1];
        float*       hnext = g_hb[(t + 1) & 1];
        const float* h0p = hprev + (size_t)(rowbase + sr0) * HH + skq * 4;
        const float* h1p = hprev + (size_t)(rowbase + sr1) * HH + skq * 4;

        float4 xwv[4];
        if (kh == 0) {
#pragma unroll
            for (int r = 0; r < 4; r++) {
                int tc = t < len_r[r] ? t : len_r[r] - 1;
                xwv[r] = *(const float4*)(g_xw + (size_t)(offs_r[r] + tc) * G4 + u * 4);
            }
        }

        ull acc[4][4];
#pragma unroll
        for (int r = 0; r < 4; r++)
#pragma unroll
            for (int c = 0; c < 4; c++) acc[r][c] = 0ull;

        float4 pa = __ldcg((const float4*)h0p);
        float4 pb = __ldcg((const float4*)h1p);
        sH[(skq*2  )*64 + sr0] = pk2(pa.x, pa.y);
        sH[(skq*2+1)*64 + sr0] = pk2(pa.z, pa.w);
        sH[(skq*2  )*64 + sr1] = pk2(pb.x, pb.y);
        sH[(skq*2+1)*64 + sr1] = pk2(pb.z, pb.w);
        pa = __ldcg((const float4*)(h0p + 32));
        pb = __ldcg((const float4*)(h1p + 32));
        __syncthreads();

        for (int ch = 0; ch < 16; ch++) {
            const ull* hb = sH + (ch & 1) * 1024;
            if (ch < 15) {
                ull* nb = sH + ((ch + 1) & 1) * 1024;
                nb[(skq*2  )*64 + sr0] = pk2(pa.x, pa.y);
                nb[(skq*2+1)*64 + sr0] = pk2(pa.z, pa.w);
                nb[(skq*2  )*64 + sr1] = pk2(pb.x, pb.y);
                nb[(skq*2+1)*64 + sr1] = pk2(pb.z, pb.w);
                if (ch < 14) {
                    pa = __ldcg((const float4*)(h0p + (ch + 2) * 32));
                    pb = __ldcg((const float4*)(h1p + (ch + 2) * 32));
                }
            }
            const ull* wbase = sWp + (ch * 16 + kh * 8) * 32 + tx * 4;
            const ull* hbase = hb + (kh * 8) * 64 + ty4;
#pragma unroll
            for (int j = 0; j < 8; j++) {
                ulonglong2 hA = *(const ulonglong2*)(hbase + j * 64);
                ulonglong2 hB = *(const ulonglong2*)(hbase + j * 64 + 2);
                ulonglong2 wA = *(const ulonglong2*)(wbase + j * 32);
                ulonglong2 wB = *(const ulonglong2*)(wbase + j * 32 + 2);
                acc[0][0]=ffma2(hA.x,wA.x,acc[0][0]); acc[0][1]=ffma2(hA.x,wA.y,acc[0][1]);
                acc[0][2]=ffma2(hA.x,wB.x,acc[0][2]); acc[0][3]=ffma2(hA.x,wB.y,acc[0][3]);
                acc[1][0]=ffma2(hA.y,wA.x,acc[1][0]); acc[1][1]=ffma2(hA.y,wA.y,acc[1][1]);
                acc[1][2]=ffma2(hA.y,wB.x,acc[1][2]); acc[1][3]=ffma2(hA.y,wB.y,acc[1][3]);
                acc[2][0]=ffma2(hB.x,wA.x,acc[2][0]); acc[2][1]=ffma2(hB.x,wA.y,acc[2][1]);
                acc[2][2]=ffma2(hB.x,wB.x,acc[2][2]); acc[2][3]=ffma2(hB.x,wB.y,acc[2][3]);
                acc[3][0]=ffma2(hB.y,wA.x,acc[3][0]); acc[3][1]=ffma2(hB.y,wA.y,acc[3][1]);
                acc[3][2]=ffma2(hB.y,wB.x,acc[3][2]); acc[3][3]=ffma2(hB.y,wB.y,acc[3][3]);
            }
            __syncthreads();
        }

        if (kh == 1) {
#pragma unroll
            for (int r = 0; r < 4; r++)
#pragma unroll
                for (int c = 0; c < 4; c++)
                    red[tid2 * 16 + r * 4 + c] = acc[r][c];
        }
        __syncthreads();

        if (kh == 0) {
#pragma unroll
            for (int r = 0; r < 4; r++) {
                float2 a0 = unpk(acc[r][0]), b0 = unpk(red[tid2*16 + r*4 + 0]);
                float2 a1 = unpk(acc[r][1]), b1 = unpk(red[tid2*16 + r*4 + 1]);
                float2 a2 = unpk(acc[r][2]), b2 = unpk(red[tid2*16 + r*4 + 2]);
                float2 a3 = unpk(acc[r][3]), b3 = unpk(red[tid2*16 + r*4 + 3]);
                float gi = a0.x + a0.y + b0.x + b0.y + xwv[r].x;
                float gf = a1.x + a1.y + b1.x + b1.y + xwv[r].y;
                float gg = a2.x + a2.y + b2.x + b2.y + xwv[r].z;
                float go = a3.x + a3.y + b3.x + b3.y + xwv[r].w;
                float si = sigf(gi), sf = sigf(gf), so = sigf(go);
                float tg = fast_tanh(gg);
                creg[r] = sf * creg[r] + si * tg;
                float h = so * fast_tanh(creg[r]);
                int row = rowbase + ty4 + r;
                hnext[(size_t)row * HH + u] = h;
                if (t < len_r[r]) g_hs[(size_t)(offs_r[r] + t) * HH + u] = h;
            }
        }

        __threadfence();
        __syncthreads();
        if (tid == 0) {
            atomicAdd(&g_bar, 1u);
            unsigned need = (unsigned)(t + 1) * 128u;
            while (*(volatile unsigned*)&g_bar < need) __nanosleep(64);
        }
        __syncthreads();
    }
}

// ---------- ragged pack ----------
__global__ void pack_kernel(const float* __restrict__ state, int N)
{
    int idx = blockIdx.x * 256 + threadIdx.x;
    if (idx >= N * 192) return;
    int r = idx / 192, c = idx % 192;
    float4 v;
    if (c < 64) v = *(const float4*)(state + (size_t)g_rowidx[r] * DD + c * 4);
    else        v = *(const float4*)(g_hs + (size_t)r * HH + (c - 64) * 4);
    *(float4*)(g_inp + (size_t)r * (DD + HH) + c * 4) = v;
}

// ---------- thin output heads ----------
__global__ void head_kernel(const float* __restrict__ X, const float* __restrict__ Wh,
                            const float* __restrict__ bh, float* __restrict__ out,
                            int N, int nout, int do_tanh)
{
    __shared__ float sw[3 * 512];
    int tid = threadIdx.x;
    for (int i = tid; i < nout * 512; i += 256) sw[i] = Wh[i];
    __syncthreads();
    int warp = tid >> 5, lane = tid & 31;
    int r = blockIdx.x * 8 + warp;
    if (r >= N) return;
    const float* x = X + (size_t)r * 512;
    float s0 = 0.f, s1 = 0.f, s2 = 0.f;
    for (int k = lane; k < 512; k += 32) {
        float v = x[k];
        s0 += v * sw[k];
        if (nout > 1) { s1 += v * sw[512 + k]; s2 += v * sw[1024 + k]; }
    }
#pragma unroll
    for (int o = 16; o; o >>= 1) {
        s0 += __shfl_xor_sync(0xffffffffu, s0, o);
        s1 += __shfl_xor_sync(0xffffffffu, s1, o);
        s2 += __shfl_xor_sync(0xffffffffu, s2, o);
    }
    if (lane == 0) {
        float v0 = s0 + bh[0]; if (do_tanh) v0 = tanhf(v0);
        out[(size_t)r * nout + 0] = v0;
        if (nout > 1) {
            float v1 = s1 + bh[1]; if (do_tanh) v1 = tanhf(v1);
            float v2 = s2 + bh[2]; if (do_tanh) v2 = tanhf(v2);
            out[(size_t)r * nout + 1] = v1;
            out[(size_t)r * nout + 2] = v2;
        }
    }
}

// ---------- launch ----------
extern "C" void kernel_launch(void* const* d_in, const int* in_sizes, int n_in,
                              void* d_out, int out_size)
{
    const float* state = (const float*)d_in[0];
    const float* h0    = (const float*)d_in[1];
    const int*   lens  = (const int*)  d_in[3];
    const float* W_ih  = (const float*)d_in[4];
    const float* W_hh  = (const float*)d_in[5];
    const float* b_ih  = (const float*)d_in[6];
    const float* b_hh  = (const float*)d_in[7];
    const float* aw0 = (const float*)d_in[8];  const float* ab0 = (const float*)d_in[9];
    const float* aw1 = (const float*)d_in[10]; const float* ab1 = (const float*)d_in[11];
    const float* aw2 = (const float*)d_in[12]; const float* ab2 = (const float*)d_in[13];
    const float* cw0 = (const float*)d_in[14]; const float* cb0 = (const float*)d_in[15];
    const float* cw1 = (const float*)d_in[16]; const float* cb1 = (const float*)d_in[17];
    const float* cw2 = (const float*)d_in[18]; const float* cb2 = (const float*)d_in[19];
    float* out = (float*)d_out;

    const int N = out_size / 4;

    float *p_xw, *p_inp, *p_m1, *p_m2;
    int   *p_ridx;
    cudaGetSymbolAddress((void**)&p_xw,   g_xw);
    cudaGetSymbolAddress((void**)&p_inp,  g_inp);
    cudaGetSymbolAddress((void**)&p_m1,   g_m1);
    cudaGetSymbolAddress((void**)&p_m2,   g_m2);
    cudaGetSymbolAddress((void**)&p_ridx, g_rowidx);

    static int attr_set = 0;
    if (!attr_set) {
        cudaFuncSetAttribute(lstm_persist,
            cudaFuncAttributeMaxDynamicSharedMemorySize, 81920);
        cudaFuncSetAttribute(tgemm_mma,
            cudaFuncAttributeMaxDynamicSharedMemorySize, TG_SMEM);
        attr_set = 1;
    }

    scan_kernel<<<1, 128>>>(lens);
    init_kernel<<<(BB * HH + 255) / 256, 256>>>(h0);
    rowmap_kernel<<<BB, 128>>>(lens);

    const int MT = (N + 127) / 128;
    tgemm_mma<<<dim3(MT, 16), 256, TG_SMEM>>>(
        state, p_ridx, W_ih, b_ih, b_hh, p_xw, N, G4, DD, 0, 1);

    lstm_persist<<<128, 256, 81920>>>(W_hh, lens);

    pack_kernel<<<(N * 192 + 255) / 256, 256>>>(state, N);

    tgemm_mma<<<dim3(MT, 4), 256, TG_SMEM>>>(p_inp, nullptr, aw0, ab0, nullptr, p_m1, N, MID, DD + HH, 1, 0);
    tgemm_mma<<<dim3(MT, 4), 256, TG_SMEM>>>(p_m1,  nullptr, aw1, ab1, nullptr, p_m2, N, MID, MID, 1, 0);
    head_kernel<<<(N + 7) / 8, 256>>>(p_m2, aw2, ab2, out, N, 3, 1);
    tgemm_mma<<<dim3(MT, 4), 256, TG_SMEM>>>(p_inp, nullptr, cw0, cb0, nullptr, p_m1, N, MID, DD + HH, 1, 0);
    tgemm_mma<<<dim3(MT, 4), 256, TG_SMEM>>>(p_m1,  nullptr, cw1, cb1, nullptr, p_m2, N, MID, MID, 1, 0);
    head_kernel<<<(N + 7) / 8, 256>>>(p_m2, cw2, cb2, out + (size_t)3 * N, N, 1, 0);
}